// round 1
// baseline (speedup 1.0000x reference)
#include <cuda_runtime.h>
#include <math.h>

// Problem constants (MultiHeadLatentAttention): B=2, T=2048, D=2048
#define H_    16
#define T_    2048
#define B_    2
#define D_    2048
#define QKD_  192
#define NOPE_ 128
#define ROPE_ 64
#define KVR_  512
#define VD_   128
#define NT_   (B_ * T_)          // 4096 tokens total

// ---------------- scratch (static device globals; no allocations) ----------
__device__ float g_q     [NT_ * H_ * QKD_];        // 12.58M  (q after rope, [tok, h, 192])
__device__ float g_kvc   [NT_ * (KVR_ + ROPE_)];   //  2.36M  (x @ wkv_a)
__device__ float g_kvlat [NT_ * KVR_];             //  2.10M  (rmsnormed latent)
__device__ float g_krope [NT_ * ROPE_];            //  0.26M  (roped k_rope, shared across heads)
__device__ float g_kvfull[NT_ * H_ * (NOPE_+VD_)]; // 16.78M  ([tok, h, 256] = k_nope|v)
__device__ float g_y     [NT_ * H_ * VD_];         //  8.39M  (attention output, [tok, h*128])

// ---------------- generic fp32 GEMM: C[M,N] = A[M,K] @ B[K,N] --------------
// 128x128 block tile, BK=16, 256 threads, 8x8 per-thread microtile.
// Requires: M % 128 == 0, K % 16 == 0, N % 4 == 0 (N boundary guarded).
__global__ __launch_bounds__(256) void sgemm_kernel(
    const float* __restrict__ A, const float* __restrict__ B,
    float* __restrict__ C, int M, int N, int K)
{
    const int BK = 16;
    __shared__ float As[16][132];   // transposed A tile, padded
    __shared__ float Bs[16][128];

    int tid  = threadIdx.x;
    int bx   = blockIdx.x, by = blockIdx.y;
    int trow = tid >> 4, tcol = tid & 15;

    float acc[8][8];
#pragma unroll
    for (int m = 0; m < 8; m++)
#pragma unroll
        for (int n = 0; n < 8; n++) acc[m][n] = 0.f;

    const float* Ab = A + (size_t)by * 128 * K;

    for (int k0 = 0; k0 < K; k0 += BK) {
        // A tile: 128 rows x 16 cols = 512 float4 loads (transposed store)
#pragma unroll
        for (int it = 0; it < 2; it++) {
            int i = tid + it * 256;
            int r = i >> 2;
            int c = (i & 3) << 2;
            float4 a4 = *(const float4*)(Ab + (size_t)r * K + k0 + c);
            As[c + 0][r] = a4.x; As[c + 1][r] = a4.y;
            As[c + 2][r] = a4.z; As[c + 3][r] = a4.w;
        }
        // B tile: 16 rows x 128 cols = 512 float4 loads (N-guarded)
#pragma unroll
        for (int it = 0; it < 2; it++) {
            int i = tid + it * 256;
            int r = i >> 5;
            int c = (i & 31) << 2;
            int gcol = bx * 128 + c;
            float4 b4 = make_float4(0.f, 0.f, 0.f, 0.f);
            if (gcol < N) b4 = *(const float4*)(B + (size_t)(k0 + r) * N + gcol);
            *(float4*)&Bs[r][c] = b4;
        }
        __syncthreads();

#pragma unroll
        for (int kk = 0; kk < BK; kk++) {
            float4 a0 = *(const float4*)&As[kk][trow * 8];
            float4 a1 = *(const float4*)&As[kk][trow * 8 + 4];
            float4 b0 = *(const float4*)&Bs[kk][tcol * 8];
            float4 b1 = *(const float4*)&Bs[kk][tcol * 8 + 4];
            float ar[8] = {a0.x, a0.y, a0.z, a0.w, a1.x, a1.y, a1.z, a1.w};
            float br[8] = {b0.x, b0.y, b0.z, b0.w, b1.x, b1.y, b1.z, b1.w};
#pragma unroll
            for (int m = 0; m < 8; m++)
#pragma unroll
                for (int n = 0; n < 8; n++)
                    acc[m][n] = fmaf(ar[m], br[n], acc[m][n]);
        }
        __syncthreads();
    }

#pragma unroll
    for (int m = 0; m < 8; m++) {
        int row = by * 128 + trow * 8 + m;
#pragma unroll
        for (int n = 0; n < 8; n += 4) {
            int col = bx * 128 + tcol * 8 + n;
            if (col < N) {
                float4 v = make_float4(acc[m][n], acc[m][n+1], acc[m][n+2], acc[m][n+3]);
                *(float4*)(C + (size_t)row * N + col) = v;
            }
        }
    }
}

// ---------------- RMSNorm over latent (first 512 of kvc) -------------------
__global__ __launch_bounds__(256) void rmsnorm_kernel(
    const float* __restrict__ kvc, const float* __restrict__ w,
    float* __restrict__ kvlat)
{
    int token = blockIdx.x;
    int tid = threadIdx.x;
    const float* src = kvc + (size_t)token * (KVR_ + ROPE_);
    float v0 = src[tid], v1 = src[tid + 256];
    float ss = v0 * v0 + v1 * v1;
#pragma unroll
    for (int o = 16; o > 0; o >>= 1) ss += __shfl_xor_sync(0xffffffffu, ss, o);

    __shared__ float red[8];
    __shared__ float nrm_s;
    if ((tid & 31) == 0) red[tid >> 5] = ss;
    __syncthreads();
    if (tid == 0) {
        float s = 0.f;
#pragma unroll
        for (int i = 0; i < 8; i++) s += red[i];
        nrm_s = rsqrtf(s * (1.f / 512.f) + 1e-6f);
    }
    __syncthreads();
    float nrm = nrm_s;
    kvlat[(size_t)token * KVR_ + tid]       = v0 * nrm * w[tid];
    kvlat[(size_t)token * KVR_ + tid + 256] = v1 * nrm * w[tid + 256];
}

// ---------------- RoPE ------------------------------------------------------
// angle(t, j) = t * 10000^{-j/32}; out[j]=x1*c - x2*s, out[j+32]=x2*c + x1*s
__global__ void krope_kernel(const float* __restrict__ kvc, float* __restrict__ kr)
{
    int idx = blockIdx.x * blockDim.x + threadIdx.x;  // NT_*32
    if (idx >= NT_ * 32) return;
    int j = idx & 31;
    int token = idx >> 5;
    int t = token & (T_ - 1);
    float inv = powf(10000.f, -(float)j * (1.f / 32.f));
    float s, c;
    sincosf((float)t * inv, &s, &c);
    const float* src = kvc + (size_t)token * (KVR_ + ROPE_) + KVR_;
    float x1 = src[j], x2 = src[j + 32];
    kr[(size_t)token * ROPE_ + j]      = x1 * c - x2 * s;
    kr[(size_t)token * ROPE_ + 32 + j] = x2 * c + x1 * s;
}

__global__ void qrope_kernel(float* __restrict__ q)
{
    int idx = blockIdx.x * blockDim.x + threadIdx.x;  // NT_*H_*32
    if (idx >= NT_ * H_ * 32) return;
    int j   = idx & 31;
    int bth = idx >> 5;                 // (b*T + t)*H + h
    int t   = (bth / H_) & (T_ - 1);
    float inv = powf(10000.f, -(float)j * (1.f / 32.f));
    float s, c;
    sincosf((float)t * inv, &s, &c);
    float* p = q + (size_t)bth * QKD_ + NOPE_;
    float x1 = p[j], x2 = p[j + 32];
    p[j]      = x1 * c - x2 * s;
    p[j + 32] = x2 * c + x1 * s;
}

// ---------------- fused causal flash attention ------------------------------
// grid (T/64, B*H), 256 threads, 1 block handles 64 q rows for one (b,h).
// K tile assembled in smem from kv_full[...,:128] and broadcast g_krope.
#define FA_SMEM_FLOATS (192*65 + 192*65 + 64*132 + 64*65 + 3*64)

__global__ __launch_bounds__(256) void flash_kernel(
    const float* __restrict__ q, const float* __restrict__ kvfull,
    const float* __restrict__ krope, float* __restrict__ y)
{
    extern __shared__ float sm[];
    float* Qs   = sm;                    // [k=192][row=64], stride 65 (transposed)
    float* Ks   = Qs + 192 * 65;         // [k=192][row=64], stride 65
    float* Vs   = Ks + 192 * 65;         // [row=64][d=128], stride 132
    float* Ps   = Vs + 64 * 132;         // [row=64][col=64], stride 65
    float* m_sm = Ps + 64 * 65;
    float* l_sm = m_sm + 64;
    float* c_sm = l_sm + 64;

    int tid  = threadIdx.x;
    int qblk = blockIdx.x;
    int bh   = blockIdx.y;
    int b = bh >> 4, h = bh & 15;
    int trow = tid >> 4, tcol = tid & 15;
    int q0 = qblk * 64;
    size_t tokbase = (size_t)b * T_;

    // Load Q tile (transposed) + init online-softmax state
    for (int i = tid; i < 64 * 192; i += 256) {
        int r = i / 192, k = i - r * 192;
        Qs[k * 65 + r] = q[((tokbase + q0 + r) * H_ + h) * QKD_ + k];
    }
    if (tid < 64) { m_sm[tid] = -INFINITY; l_sm[tid] = 0.f; }

    float oacc[4][8];
#pragma unroll
    for (int m = 0; m < 4; m++)
#pragma unroll
        for (int n = 0; n < 8; n++) oacc[m][n] = 0.f;

    const float scale = 0.07216878364870322f;   // 1/sqrt(192)

    for (int kt = 0; kt <= qblk; kt++) {
        int k0 = kt * 64;
        __syncthreads();   // Q/prev-PV done before overwriting K/V

        // K tile transposed: first 128 dims from kv_full k_nope, last 64 from krope
        for (int i = tid; i < 64 * 192; i += 256) {
            int r = i / 192, k = i - r * 192;
            size_t tok = tokbase + k0 + r;
            float v = (k < 128) ? kvfull[(tok * H_ + h) * 256 + k]
                                : krope[tok * 64 + (k - 128)];
            Ks[k * 65 + r] = v;
        }
        // V tile
        for (int i = tid; i < 64 * 128; i += 256) {
            int r = i >> 7, d = i & 127;
            Vs[r * 132 + d] = kvfull[((tokbase + k0 + r) * H_ + h) * 256 + 128 + d];
        }
        __syncthreads();

        // S = Q @ K^T  (each thread 4x4 of 64x64)
        float sacc[4][4];
#pragma unroll
        for (int m = 0; m < 4; m++)
#pragma unroll
            for (int n = 0; n < 4; n++) sacc[m][n] = 0.f;
#pragma unroll 4
        for (int kk = 0; kk < 192; kk++) {
            float ar[4], br[4];
#pragma unroll
            for (int m = 0; m < 4; m++) ar[m] = Qs[kk * 65 + trow * 4 + m];
#pragma unroll
            for (int n = 0; n < 4; n++) br[n] = Ks[kk * 65 + tcol * 4 + n];
#pragma unroll
            for (int m = 0; m < 4; m++)
#pragma unroll
                for (int n = 0; n < 4; n++)
                    sacc[m][n] = fmaf(ar[m], br[n], sacc[m][n]);
        }
        // scale + causal mask, stage into Ps
#pragma unroll
        for (int m = 0; m < 4; m++) {
            int qi = q0 + trow * 4 + m;
#pragma unroll
            for (int n = 0; n < 4; n++) {
                int ki = k0 + tcol * 4 + n;
                Ps[(trow * 4 + m) * 65 + tcol * 4 + n] =
                    (ki <= qi) ? sacc[m][n] * scale : -INFINITY;
            }
        }
        __syncthreads();

        // online softmax: 4 threads per row, 16 cols each
        {
            int r = tid >> 2, seg = tid & 3;
            float mo = m_sm[r];
            float mx = -INFINITY;
#pragma unroll
            for (int j = 0; j < 16; j++)
                mx = fmaxf(mx, Ps[r * 65 + seg * 16 + j]);
            mx = fmaxf(mx, __shfl_xor_sync(0xffffffffu, mx, 1));
            mx = fmaxf(mx, __shfl_xor_sync(0xffffffffu, mx, 2));
            float mnew = fmaxf(mo, mx);
            float sum = 0.f;
#pragma unroll
            for (int j = 0; j < 16; j++) {
                float p = expf(Ps[r * 65 + seg * 16 + j] - mnew);
                Ps[r * 65 + seg * 16 + j] = p;
                sum += p;
            }
            sum += __shfl_xor_sync(0xffffffffu, sum, 1);
            sum += __shfl_xor_sync(0xffffffffu, sum, 2);
            if (seg == 0) {
                float cf = expf(mo - mnew);
                c_sm[r] = cf;
                l_sm[r] = l_sm[r] * cf + sum;
                m_sm[r] = mnew;
            }
        }
        __syncthreads();

        // O = O*corr + P @ V  (each thread 4 rows x 8 cols of 64x128)
        float cm[4];
#pragma unroll
        for (int m = 0; m < 4; m++) cm[m] = c_sm[trow * 4 + m];
#pragma unroll
        for (int m = 0; m < 4; m++)
#pragma unroll
            for (int n = 0; n < 8; n++) oacc[m][n] *= cm[m];
#pragma unroll 2
        for (int j = 0; j < 64; j++) {
            float pv[4];
#pragma unroll
            for (int m = 0; m < 4; m++) pv[m] = Ps[(trow * 4 + m) * 65 + j];
            float4 v0 = *(const float4*)&Vs[j * 132 + tcol * 8];
            float4 v1 = *(const float4*)&Vs[j * 132 + tcol * 8 + 4];
            float vv[8] = {v0.x, v0.y, v0.z, v0.w, v1.x, v1.y, v1.z, v1.w};
#pragma unroll
            for (int m = 0; m < 4; m++)
#pragma unroll
                for (int n = 0; n < 8; n++)
                    oacc[m][n] = fmaf(pv[m], vv[n], oacc[m][n]);
        }
    }

    // finalize: divide by l, write y[tok, h*128 + col]
#pragma unroll
    for (int m = 0; m < 4; m++) {
        int i = trow * 4 + m;
        float linv = 1.f / l_sm[i];
        size_t row = tokbase + q0 + i;
        float4 o0 = make_float4(oacc[m][0]*linv, oacc[m][1]*linv,
                                oacc[m][2]*linv, oacc[m][3]*linv);
        float4 o1 = make_float4(oacc[m][4]*linv, oacc[m][5]*linv,
                                oacc[m][6]*linv, oacc[m][7]*linv);
        float* yp = y + row * (H_ * VD_) + h * VD_ + tcol * 8;
        *(float4*)(yp)     = o0;
        *(float4*)(yp + 4) = o1;
    }
}

// ---------------- launch ----------------------------------------------------
extern "C" void kernel_launch(void* const* d_in, const int* in_sizes, int n_in,
                              void* d_out, int out_size)
{
    const float* x     = (const float*)d_in[0];   // [B,T,D]
    const float* wq    = (const float*)d_in[1];   // [D, H*QKD]
    const float* wkv_a = (const float*)d_in[2];   // [D, KVR+ROPE]
    const float* wkv_b = (const float*)d_in[3];   // [KVR, H*(NOPE+VD)]
    const float* wo    = (const float*)d_in[4];   // [H*VD, D]
    const float* kvw   = (const float*)d_in[5];   // [KVR]
    float* out = (float*)d_out;                   // [B,T,D] fp32

    float *q, *kvc, *kvlat, *kr, *kvfull, *y;
    cudaGetSymbolAddress((void**)&q,      g_q);
    cudaGetSymbolAddress((void**)&kvc,    g_kvc);
    cudaGetSymbolAddress((void**)&kvlat,  g_kvlat);
    cudaGetSymbolAddress((void**)&kr,     g_krope);
    cudaGetSymbolAddress((void**)&kvfull, g_kvfull);
    cudaGetSymbolAddress((void**)&y,      g_y);

    cudaFuncSetAttribute(flash_kernel,
        cudaFuncAttributeMaxDynamicSharedMemorySize, FA_SMEM_FLOATS * 4);

    // 1) q = x @ wq                      [4096, 3072]
    sgemm_kernel<<<dim3(24, 32), 256>>>(x, wq, q, NT_, H_ * QKD_, D_);
    // 2) kvc = x @ wkv_a                 [4096, 576]
    sgemm_kernel<<<dim3(5, 32), 256>>>(x, wkv_a, kvc, NT_, KVR_ + ROPE_, D_);
    // 3) RMSNorm latent
    rmsnorm_kernel<<<NT_, 256>>>(kvc, kvw, kvlat);
    // 4) RoPE on k_rope (shared across heads)
    krope_kernel<<<(NT_ * 32 + 255) / 256, 256>>>(kvc, kr);
    // 5) RoPE on q (in place on last 64 dims)
    qrope_kernel<<<(NT_ * H_ * 32 + 255) / 256, 256>>>(q);
    // 6) kv_full = kv_latent @ wkv_b     [4096, 4096]
    sgemm_kernel<<<dim3(32, 32), 256>>>(kvlat, wkv_b, kvfull, NT_, H_ * (NOPE_ + VD_), KVR_);
    // 7) fused causal attention -> y     [4096, 2048]
    flash_kernel<<<dim3(T_ / 64, B_ * H_), 256, FA_SMEM_FLOATS * 4>>>(q, kvfull, kr, y);
    // 8) out = y @ wo                    [4096, 2048]
    sgemm_kernel<<<dim3(16, 32), 256>>>(y, wo, out, NT_, D_, H_ * VD_);
}

// round 11
// speedup vs baseline: 6.5646x; 6.5646x over previous
#include <cuda_runtime.h>
#include <math.h>

// Problem constants (MultiHeadLatentAttention): B=2, T=2048, D=2048
#define H_    16
#define T_    2048
#define B_    2
#define D_    2048
#define QKD_  192
#define NOPE_ 128
#define ROPE_ 64
#define KVR_  512
#define VD_   128
#define NT_   (B_ * T_)          // 4096 tokens total

// ---------------- scratch (static device globals; no allocations) ----------
__device__ float g_q     [NT_ * H_ * QKD_];
__device__ float g_kvc   [NT_ * (KVR_ + ROPE_)];
__device__ float g_kvlat [NT_ * KVR_];
__device__ float g_krope [NT_ * ROPE_];
__device__ float g_kvfull[NT_ * H_ * (NOPE_+VD_)];
__device__ float g_y     [NT_ * H_ * VD_];

// ---------------- tf32 helpers ---------------------------------------------
__device__ __forceinline__ unsigned f2tf32(float f) {
    unsigned u;
    asm("cvt.rna.tf32.f32 %0, %1;" : "=r"(u) : "f"(f));
    return u;
}

__device__ __forceinline__ void mma_tf32(float c[4],
    unsigned a0, unsigned a1, unsigned a2, unsigned a3,
    unsigned b0, unsigned b1)
{
    asm volatile(
        "mma.sync.aligned.m16n8k8.row.col.f32.tf32.tf32.f32 "
        "{%0,%1,%2,%3}, {%4,%5,%6,%7}, {%8,%9}, {%0,%1,%2,%3};"
        : "+f"(c[0]), "+f"(c[1]), "+f"(c[2]), "+f"(c[3])
        : "r"(a0), "r"(a1), "r"(a2), "r"(a3), "r"(b0), "r"(b1));
}

// ---------------- tf32 tensor-core GEMM: C[M,N] = A[M,K] @ B[K,N] ----------
// 128x128 block tile, BK=32, 256 threads = 8 warps (2x4), warp tile 64x32.
// As row-major stride 36 (=4 mod 32): a-frag bank = 4*gr+q -> conflict-free.
// Bs row(k)-major stride 136 (=8 mod 32): b-frag bank = 8*q+gr -> conflict-free.
__global__ __launch_bounds__(256) void tgemm_kernel(
    const float* __restrict__ A, const float* __restrict__ B,
    float* __restrict__ C, int M, int N, int K)
{
    __shared__ unsigned As[128][36];   // [m][k] tf32
    __shared__ unsigned Bs[32][136];   // [k][n] tf32

    int tid  = threadIdx.x;
    int bx   = blockIdx.x, by = blockIdx.y;
    int warp = tid >> 5, lane = tid & 31;
    int wm = warp >> 2, wn = warp & 3;     // 2 warp-rows x 4 warp-cols
    int gr = lane >> 2, q = lane & 3;      // frag row-group / quad

    float acc[4][4][4];
#pragma unroll
    for (int mi = 0; mi < 4; mi++)
#pragma unroll
        for (int ni = 0; ni < 4; ni++)
#pragma unroll
            for (int r = 0; r < 4; r++) acc[mi][ni][r] = 0.f;

    const float* Ab = A + (size_t)by * 128 * K;

    for (int k0 = 0; k0 < K; k0 += 32) {
        // A tile: 128 rows x 32 k, natural [m][k], uint4 stores
#pragma unroll
        for (int it = 0; it < 4; it++) {
            int i  = tid + it * 256;
            int r  = i >> 3;
            int c4 = (i & 7) << 2;
            float4 a4 = *(const float4*)(Ab + (size_t)r * K + k0 + c4);
            uint4 u = make_uint4(f2tf32(a4.x), f2tf32(a4.y),
                                 f2tf32(a4.z), f2tf32(a4.w));
            *(uint4*)&As[r][c4] = u;
        }
        // B tile: 32 k x 128 n (N-guarded), uint4 stores
#pragma unroll
        for (int it = 0; it < 4; it++) {
            int i = tid + it * 256;
            int r = i >> 5;
            int c = (i & 31) << 2;
            int gcol = bx * 128 + c;
            float4 b4 = make_float4(0.f, 0.f, 0.f, 0.f);
            if (gcol < N) b4 = *(const float4*)(B + (size_t)(k0 + r) * N + gcol);
            uint4 u = make_uint4(f2tf32(b4.x), f2tf32(b4.y),
                                 f2tf32(b4.z), f2tf32(b4.w));
            *(uint4*)&Bs[r][c] = u;
        }
        __syncthreads();

#pragma unroll
        for (int ks = 0; ks < 4; ks++) {
            int kb = ks * 8;
            unsigned afr[4][4];
#pragma unroll
            for (int mi = 0; mi < 4; mi++) {
                int m0 = wm * 64 + mi * 16 + gr;
                afr[mi][0] = As[m0][kb + q];
                afr[mi][1] = As[m0 + 8][kb + q];
                afr[mi][2] = As[m0][kb + q + 4];
                afr[mi][3] = As[m0 + 8][kb + q + 4];
            }
            unsigned bfr[4][2];
#pragma unroll
            for (int ni = 0; ni < 4; ni++) {
                int n0 = wn * 32 + ni * 8 + gr;
                bfr[ni][0] = Bs[kb + q][n0];
                bfr[ni][1] = Bs[kb + q + 4][n0];
            }
#pragma unroll
            for (int mi = 0; mi < 4; mi++)
#pragma unroll
                for (int ni = 0; ni < 4; ni++)
                    mma_tf32(acc[mi][ni],
                             afr[mi][0], afr[mi][1], afr[mi][2], afr[mi][3],
                             bfr[ni][0], bfr[ni][1]);
        }
        __syncthreads();
    }

    // epilogue: c0=(gr, 2q), c1=(gr, 2q+1), c2=(gr+8, 2q), c3=(gr+8, 2q+1)
#pragma unroll
    for (int mi = 0; mi < 4; mi++) {
        int row = by * 128 + wm * 64 + mi * 16 + gr;
#pragma unroll
        for (int ni = 0; ni < 4; ni++) {
            int col = bx * 128 + wn * 32 + ni * 8 + q * 2;
            if (col < N) {
                *(float2*)(C + (size_t)row * N + col) =
                    make_float2(acc[mi][ni][0], acc[mi][ni][1]);
                *(float2*)(C + (size_t)(row + 8) * N + col) =
                    make_float2(acc[mi][ni][2], acc[mi][ni][3]);
            }
        }
    }
}

// ---------------- RMSNorm over latent (first 512 of kvc) -------------------
__global__ __launch_bounds__(256) void rmsnorm_kernel(
    const float* __restrict__ kvc, const float* __restrict__ w,
    float* __restrict__ kvlat)
{
    int token = blockIdx.x;
    int tid = threadIdx.x;
    const float* src = kvc + (size_t)token * (KVR_ + ROPE_);
    float v0 = src[tid], v1 = src[tid + 256];
    float ss = v0 * v0 + v1 * v1;
#pragma unroll
    for (int o = 16; o > 0; o >>= 1) ss += __shfl_xor_sync(0xffffffffu, ss, o);

    __shared__ float red[8];
    __shared__ float nrm_s;
    if ((tid & 31) == 0) red[tid >> 5] = ss;
    __syncthreads();
    if (tid == 0) {
        float s = 0.f;
#pragma unroll
        for (int i = 0; i < 8; i++) s += red[i];
        nrm_s = rsqrtf(s * (1.f / 512.f) + 1e-6f);
    }
    __syncthreads();
    float nrm = nrm_s;
    kvlat[(size_t)token * KVR_ + tid]       = v0 * nrm * w[tid];
    kvlat[(size_t)token * KVR_ + tid + 256] = v1 * nrm * w[tid + 256];
}

// ---------------- RoPE ------------------------------------------------------
// angle(t, j) = t * 10000^{-j/32} = t * exp2(-j * log2(10000)/32)
#define NEG_L2_10K_32 (-0.41524101186092029f)

__global__ void krope_kernel(const float* __restrict__ kvc, float* __restrict__ kr)
{
    int idx = blockIdx.x * blockDim.x + threadIdx.x;  // NT_*32
    if (idx >= NT_ * 32) return;
    int j = idx & 31;
    int token = idx >> 5;
    int t = token & (T_ - 1);
    float inv = exp2f((float)j * NEG_L2_10K_32);
    float s, c;
    sincosf((float)t * inv, &s, &c);
    const float* src = kvc + (size_t)token * (KVR_ + ROPE_) + KVR_;
    float x1 = src[j], x2 = src[j + 32];
    kr[(size_t)token * ROPE_ + j]      = x1 * c - x2 * s;
    kr[(size_t)token * ROPE_ + 32 + j] = x2 * c + x1 * s;
}

__global__ void qrope_kernel(float* __restrict__ q)
{
    int idx = blockIdx.x * blockDim.x + threadIdx.x;  // NT_*H_*32
    if (idx >= NT_ * H_ * 32) return;
    int j   = idx & 31;
    int bth = idx >> 5;
    int t   = (bth / H_) & (T_ - 1);
    float inv = exp2f((float)j * NEG_L2_10K_32);
    float s, c;
    sincosf((float)t * inv, &s, &c);
    float* p = q + (size_t)bth * QKD_ + NOPE_;
    float x1 = p[j], x2 = p[j + 32];
    p[j]      = x1 * c - x2 * s;
    p[j + 32] = x2 * c + x1 * s;
}

// ---------------- fused causal flash attention (tf32 tensor cores) ----------
// grid (T/64, B*H), 256 threads = 8 warps (4m x 2n). 64 q-rows per block.
// Qs/Ks: [row][d] tf32, stride 196 (=4 mod 32)  -> conflict-free frag loads
// Vs:    [k][d]  tf32, stride 136 (=8 mod 32)   -> conflict-free frag loads
// Ps:    [row][col] f32, stride 66; Pt: [row][k] tf32, stride 68
#define FQ_ 196
#define FV_ 136
#define FP_ 66
#define FT_ 68
#define OFF_QS 0
#define OFF_KS (OFF_QS + 64 * FQ_)
#define OFF_VS (OFF_KS + 64 * FQ_)
#define OFF_PS (OFF_VS + 64 * FV_)
#define OFF_PT (OFF_PS + 64 * FP_)
#define OFF_M  (OFF_PT + 64 * FT_)
#define OFF_L  (OFF_M + 64)
#define OFF_C  (OFF_L + 64)
#define FA_WORDS (OFF_C + 64)

__global__ __launch_bounds__(256) void flash_kernel(
    const float* __restrict__ q, const float* __restrict__ kvfull,
    const float* __restrict__ krope, float* __restrict__ y)
{
    extern __shared__ float sm[];
    unsigned* Qs = (unsigned*)(sm + OFF_QS);
    unsigned* Ks = (unsigned*)(sm + OFF_KS);
    unsigned* Vs = (unsigned*)(sm + OFF_VS);
    float*    Ps = sm + OFF_PS;
    unsigned* Pt = (unsigned*)(sm + OFF_PT);
    float*  m_sm = sm + OFF_M;
    float*  l_sm = sm + OFF_L;
    float*  c_sm = sm + OFF_C;

    int tid  = threadIdx.x;
    int qblk = blockIdx.x;
    int bh   = blockIdx.y;
    int b = bh >> 4, h = bh & 15;
    int warp = tid >> 5, lane = tid & 31;
    int wm = warp >> 1, wn = warp & 1;     // 4 m x 2 n warps
    int gr = lane >> 2, qd = lane & 3;
    int q0 = qblk * 64;
    size_t tokbase = (size_t)b * T_;

    // Load Q tile [64][192] natural layout, tf32, uint4 stores
#pragma unroll
    for (int it = 0; it < 12; it++) {
        int i = tid + it * 256;
        int r = i / 48;
        int c4 = (i % 48) << 2;
        float4 a4 = *(const float4*)(q + ((tokbase + q0 + r) * H_ + h) * QKD_ + c4);
        uint4 u = make_uint4(f2tf32(a4.x), f2tf32(a4.y), f2tf32(a4.z), f2tf32(a4.w));
        *(uint4*)&Qs[r * FQ_ + c4] = u;
    }
    if (tid < 64) { m_sm[tid] = -INFINITY; l_sm[tid] = 0.f; }

    float oacc[8][4];
#pragma unroll
    for (int ni = 0; ni < 8; ni++)
#pragma unroll
        for (int r = 0; r < 4; r++) oacc[ni][r] = 0.f;

    const float scale = 0.07216878364870322f;   // 1/sqrt(192)
    int r0 = wm * 16 + gr;       // this thread's first S/O row
    int r1 = r0 + 8;

    for (int kt = 0; kt <= qblk; kt++) {
        int k0 = kt * 64;
        __syncthreads();   // Q-load / prev PV done before overwriting K/V/Pt

        // K tile: k_nope [64][128] + krope [64][64] -> Ks[row][0..191]
#pragma unroll
        for (int it = 0; it < 8; it++) {
            int i = tid + it * 256;
            int r = i >> 5, c4 = (i & 31) << 2;
            float4 a4 = *(const float4*)(kvfull + ((tokbase + k0 + r) * H_ + h) * 256 + c4);
            uint4 u = make_uint4(f2tf32(a4.x), f2tf32(a4.y), f2tf32(a4.z), f2tf32(a4.w));
            *(uint4*)&Ks[r * FQ_ + c4] = u;
        }
#pragma unroll
        for (int it = 0; it < 4; it++) {
            int i = tid + it * 256;
            int r = i >> 4, c4 = (i & 15) << 2;
            float4 a4 = *(const float4*)(krope + (tokbase + k0 + r) * 64 + c4);
            uint4 u = make_uint4(f2tf32(a4.x), f2tf32(a4.y), f2tf32(a4.z), f2tf32(a4.w));
            *(uint4*)&Ks[r * FQ_ + 128 + c4] = u;
        }
        // V tile [64][128]
#pragma unroll
        for (int it = 0; it < 8; it++) {
            int i = tid + it * 256;
            int r = i >> 5, c4 = (i & 31) << 2;
            float4 a4 = *(const float4*)(kvfull + ((tokbase + k0 + r) * H_ + h) * 256 + 128 + c4);
            uint4 u = make_uint4(f2tf32(a4.x), f2tf32(a4.y), f2tf32(a4.z), f2tf32(a4.w));
            *(uint4*)&Vs[r * FV_ + c4] = u;
        }
        __syncthreads();

        // S = Q @ K^T : warp tile m16 x n32, K-dim 192
        float sacc[4][4];
#pragma unroll
        for (int ni = 0; ni < 4; ni++)
#pragma unroll
            for (int r = 0; r < 4; r++) sacc[ni][r] = 0.f;
#pragma unroll
        for (int kb = 0; kb < QKD_; kb += 8) {
            unsigned a0 = Qs[r0 * FQ_ + kb + qd];
            unsigned a1 = Qs[r1 * FQ_ + kb + qd];
            unsigned a2 = Qs[r0 * FQ_ + kb + qd + 4];
            unsigned a3 = Qs[r1 * FQ_ + kb + qd + 4];
#pragma unroll
            for (int ni = 0; ni < 4; ni++) {
                int n0 = wn * 32 + ni * 8 + gr;
                unsigned b0 = Ks[n0 * FQ_ + kb + qd];
                unsigned b1 = Ks[n0 * FQ_ + kb + qd + 4];
                mma_tf32(sacc[ni], a0, a1, a2, a3, b0, b1);
            }
        }
        // scale + causal mask -> Ps (f32)
        int qi0 = q0 + r0, qi1 = q0 + r1;
#pragma unroll
        for (int ni = 0; ni < 4; ni++) {
            int col = wn * 32 + ni * 8 + qd * 2;
            int ki0 = k0 + col, ki1 = ki0 + 1;
            Ps[r0 * FP_ + col]     = (ki0 <= qi0) ? sacc[ni][0] * scale : -INFINITY;
            Ps[r0 * FP_ + col + 1] = (ki1 <= qi0) ? sacc[ni][1] * scale : -INFINITY;
            Ps[r1 * FP_ + col]     = (ki0 <= qi1) ? sacc[ni][2] * scale : -INFINITY;
            Ps[r1 * FP_ + col + 1] = (ki1 <= qi1) ? sacc[ni][3] * scale : -INFINITY;
        }
        __syncthreads();

        // online softmax: 4 threads per row, 16 cols each; write tf32 into Pt
        {
            int r = tid >> 2, seg = tid & 3;
            float mo = m_sm[r];
            float mx = -INFINITY;
#pragma unroll
            for (int j = 0; j < 16; j++)
                mx = fmaxf(mx, Ps[r * FP_ + seg * 16 + j]);
            mx = fmaxf(mx, __shfl_xor_sync(0xffffffffu, mx, 1));
            mx = fmaxf(mx, __shfl_xor_sync(0xffffffffu, mx, 2));
            float mnew = fmaxf(mo, mx);
            float sum = 0.f;
#pragma unroll
            for (int j = 0; j < 16; j++) {
                float p = __expf(Ps[r * FP_ + seg * 16 + j] - mnew);
                Pt[r * FT_ + seg * 16 + j] = f2tf32(p);
                sum += p;
            }
            sum += __shfl_xor_sync(0xffffffffu, sum, 1);
            sum += __shfl_xor_sync(0xffffffffu, sum, 2);
            if (seg == 0) {
                float cf = __expf(mo - mnew);
                c_sm[r] = cf;
                l_sm[r] = l_sm[r] * cf + sum;
                m_sm[r] = mnew;
            }
        }
        __syncthreads();

        // O = O*corr + P @ V : warp tile m16 x n64, K-dim 64
        float cm0 = c_sm[r0], cm1 = c_sm[r1];
#pragma unroll
        for (int ni = 0; ni < 8; ni++) {
            oacc[ni][0] *= cm0; oacc[ni][1] *= cm0;
            oacc[ni][2] *= cm1; oacc[ni][3] *= cm1;
        }
#pragma unroll
        for (int kb = 0; kb < 64; kb += 8) {
            unsigned a0 = Pt[r0 * FT_ + kb + qd];
            unsigned a1 = Pt[r1 * FT_ + kb + qd];
            unsigned a2 = Pt[r0 * FT_ + kb + qd + 4];
            unsigned a3 = Pt[r1 * FT_ + kb + qd + 4];
#pragma unroll
            for (int ni = 0; ni < 8; ni++) {
                int n0 = wn * 64 + ni * 8 + gr;
                unsigned b0 = Vs[(kb + qd) * FV_ + n0];
                unsigned b1 = Vs[(kb + qd + 4) * FV_ + n0];
                mma_tf32(oacc[ni], a0, a1, a2, a3, b0, b1);
            }
        }
    }

    // finalize: divide by l, write y[tok, h*128 + col]
    float li0 = 1.f / l_sm[r0];
    float li1 = 1.f / l_sm[r1];
    float* y0 = y + (tokbase + q0 + r0) * (H_ * VD_) + h * VD_;
    float* y1 = y + (tokbase + q0 + r1) * (H_ * VD_) + h * VD_;
#pragma unroll
    for (int ni = 0; ni < 8; ni++) {
        int col = wn * 64 + ni * 8 + qd * 2;
        *(float2*)(y0 + col) = make_float2(oacc[ni][0] * li0, oacc[ni][1] * li0);
        *(float2*)(y1 + col) = make_float2(oacc[ni][2] * li1, oacc[ni][3] * li1);
    }
}

// ---------------- launch ----------------------------------------------------
extern "C" void kernel_launch(void* const* d_in, const int* in_sizes, int n_in,
                              void* d_out, int out_size)
{
    const float* x     = (const float*)d_in[0];
    const float* wq    = (const float*)d_in[1];
    const float* wkv_a = (const float*)d_in[2];
    const float* wkv_b = (const float*)d_in[3];
    const float* wo    = (const float*)d_in[4];
    const float* kvw   = (const float*)d_in[5];
    float* out = (float*)d_out;

    float *q, *kvc, *kvlat, *kr, *kvfull, *y;
    cudaGetSymbolAddress((void**)&q,      g_q);
    cudaGetSymbolAddress((void**)&kvc,    g_kvc);
    cudaGetSymbolAddress((void**)&kvlat,  g_kvlat);
    cudaGetSymbolAddress((void**)&kr,     g_krope);
    cudaGetSymbolAddress((void**)&kvfull, g_kvfull);
    cudaGetSymbolAddress((void**)&y,      g_y);

    cudaFuncSetAttribute(flash_kernel,
        cudaFuncAttributeMaxDynamicSharedMemorySize, FA_WORDS * 4);

    // 1) q = x @ wq                      [4096, 3072]
    tgemm_kernel<<<dim3(24, 32), 256>>>(x, wq, q, NT_, H_ * QKD_, D_);
    // 2) kvc = x @ wkv_a                 [4096, 576]
    tgemm_kernel<<<dim3(5, 32), 256>>>(x, wkv_a, kvc, NT_, KVR_ + ROPE_, D_);
    // 3) RMSNorm latent
    rmsnorm_kernel<<<NT_, 256>>>(kvc, kvw, kvlat);
    // 4) RoPE on k_rope (shared across heads)
    krope_kernel<<<(NT_ * 32 + 255) / 256, 256>>>(kvc, kr);
    // 5) RoPE on q (in place on last 64 dims)
    qrope_kernel<<<(NT_ * H_ * 32 + 255) / 256, 256>>>(q);
    // 6) kv_full = kv_latent @ wkv_b     [4096, 4096]
    tgemm_kernel<<<dim3(32, 32), 256>>>(kvlat, wkv_b, kvfull, NT_, H_ * (NOPE_ + VD_), KVR_);
    // 7) fused causal attention -> y     [4096, 2048]
    flash_kernel<<<dim3(T_ / 64, B_ * H_), 256, FA_WORDS * 4>>>(q, kvfull, kr, y);
    // 8) out = y @ wo                    [4096, 2048]
    tgemm_kernel<<<dim3(16, 32), 256>>>(y, wo, out, NT_, D_, H_ * VD_);
}